// round 1
// baseline (speedup 1.0000x reference)
#include <cuda_runtime.h>
#include <math.h>

#define BB 4
#define LL 1024
#define HH 768
#define NHH 12
#define EE 32
#define MPE 4
#define EMM 128      // E*MPE
#define KLNK 16
#define TYPED 20
#define NROWS 336            // 176 nodes + 160 ctx
#define FF (HH + TYPED)      // 788
#define NA 160               // att rows per batch (E + EM)

// scratch (allocation-free rule: __device__ globals)
__device__ float g_att[BB * NA * LL];   // head-mean attention rows (entities 0..31, mentions 32..159)
__device__ float g_rs[BB * NA];         // row sums for normalization

// ---------------------------------------------------------------------------
// K1: mention attention rows: g_att[b,32+m,l] = mean_h attention[b,h,pos,l]
// ---------------------------------------------------------------------------
__global__ void k_mention_att(const float* __restrict__ att,
                              const int* __restrict__ mpos) {
    int m = blockIdx.x;
    int b = blockIdx.y;
    int p = mpos[b * EMM + m] + 1;
    const float* base = att + ((size_t)b * NHH) * LL * LL + (size_t)p * LL;
    float* dst = g_att + ((size_t)b * NA + EE + m) * LL;

    float local = 0.f;
    for (int l = threadIdx.x; l < LL; l += blockDim.x) {
        float s = 0.f;
#pragma unroll
        for (int h = 0; h < NHH; h++) s += base[(size_t)h * LL * LL + l];
        s *= (1.f / NHH);
        dst[l] = s;
        local += s;
    }
    __shared__ float red[256];
    red[threadIdx.x] = local;
    __syncthreads();
    for (int off = 128; off > 0; off >>= 1) {
        if (threadIdx.x < off) red[threadIdx.x] += red[threadIdx.x + off];
        __syncthreads();
    }
    if (threadIdx.x == 0) g_rs[b * NA + EE + m] = red[0];
}

// ---------------------------------------------------------------------------
// K2: entity attention rows: mean over 4 member mentions
// ---------------------------------------------------------------------------
__global__ void k_entity_att() {
    int e = blockIdx.x;
    int b = blockIdx.y;
    const float* src = g_att + ((size_t)b * NA + EE + e * MPE) * LL;
    float* dst = g_att + ((size_t)b * NA + e) * LL;

    float local = 0.f;
    for (int l = threadIdx.x; l < LL; l += blockDim.x) {
        float s = 0.25f * (src[l] + src[LL + l] + src[2 * LL + l] + src[3 * LL + l]);
        dst[l] = s;
        local += s;
    }
    __shared__ float red[256];
    red[threadIdx.x] = local;
    __syncthreads();
    for (int off = 128; off > 0; off >>= 1) {
        if (threadIdx.x < off) red[threadIdx.x] += red[threadIdx.x + off];
        __syncthreads();
    }
    if (threadIdx.x == 0) g_rs[b * NA + e] = red[0];
}

// ---------------------------------------------------------------------------
// K3: context GEMM per batch:
//   ctx[n,h] = sum_l g_att[b,n,l]/(rs+1e-5) * seq[b,l,h]
// written to out rows 176..335 (cols 0..767)
// Tile: 32n x 128h, K-slice 32. 256 thr, 4x4 microtile.
// ---------------------------------------------------------------------------
#define TN 32
#define TH 128
#define TL 32
__global__ void k_ctx(const float* __restrict__ seq, float* __restrict__ out) {
    int b = blockIdx.z;
    int n0 = blockIdx.y * TN;
    int h0 = blockIdx.x * TH;

    __shared__ float As[TN][TL];        // [n][l] : stores coalesced, reads broadcast
    __shared__ float Bs[TL][TH];        // [l][h] : float4 reads, conflict-free
    __shared__ float inv[TN];

    int tid = threadIdx.x;
    if (tid < TN) inv[tid] = 1.f / (g_rs[b * NA + n0 + tid] + 1e-5f);

    int th = tid & 31;      // 32 h-slots per warp
    int tn = tid >> 5;      // warp id -> n group
    int hl = th * 4;
    int nl = tn * 4;

    const float* attb = g_att + (size_t)(b * NA + n0) * LL;
    const float* seqb = seq + (size_t)b * LL * HH;

    float acc[4][4] = {};

    for (int l0 = 0; l0 < LL; l0 += TL) {
        __syncthreads();
        for (int idx = tid; idx < TN * TL; idx += 256) {
            int n = idx >> 5, l = idx & 31;
            As[n][l] = attb[(size_t)n * LL + l0 + l];
        }
        for (int idx = tid; idx < TL * TH; idx += 256) {
            int l = idx >> 7, h = idx & 127;
            Bs[l][h] = seqb[(size_t)(l0 + l) * HH + h0 + h];
        }
        __syncthreads();
#pragma unroll 8
        for (int l = 0; l < TL; l++) {
            float4 bv = *(const float4*)&Bs[l][hl];
            float a0 = As[nl + 0][l];
            float a1 = As[nl + 1][l];
            float a2 = As[nl + 2][l];
            float a3 = As[nl + 3][l];
            acc[0][0] += a0 * bv.x; acc[0][1] += a0 * bv.y; acc[0][2] += a0 * bv.z; acc[0][3] += a0 * bv.w;
            acc[1][0] += a1 * bv.x; acc[1][1] += a1 * bv.y; acc[1][2] += a1 * bv.z; acc[1][3] += a1 * bv.w;
            acc[2][0] += a2 * bv.x; acc[2][1] += a2 * bv.y; acc[2][2] += a2 * bv.z; acc[2][3] += a2 * bv.w;
            acc[3][0] += a3 * bv.x; acc[3][1] += a3 * bv.y; acc[3][2] += a3 * bv.z; acc[3][3] += a3 * bv.w;
        }
    }

#pragma unroll
    for (int i = 0; i < 4; i++) {
        float s = inv[nl + i];
        float4 v = make_float4(acc[i][0] * s, acc[i][1] * s, acc[i][2] * s, acc[i][3] * s);
        float* o = out + ((size_t)b * NROWS + 176 + n0 + nl + i) * FF + h0 + hl;
        *(float4*)o = v;   // FF=788 divisible by 4, h0+hl %4==0 -> aligned
    }
}

// ---------------------------------------------------------------------------
// K4: link span pooling, deterministic (fixed-order reductions, no atomics)
//   w[c] = sum_{r in span} mean_h att[b,h,s+r,s+c]   (head mean folded in scale)
//   link_rep[h] = sum_c w[c]*seq[b,s+c,h] / (12*len)
// out rows 160..175, cols 0..767.
// ---------------------------------------------------------------------------
__global__ void k_link(const float* __restrict__ att, const float* __restrict__ seq,
                       const int* __restrict__ lstart, const int* __restrict__ llen,
                       float* __restrict__ out) {
    int k = blockIdx.x;
    int b = blockIdx.y;
    int s = lstart[b * KLNK + k] + 1;
    int len = llen[b * KLNK + k] + 1;   // 1..31

    __shared__ float part[32][4];       // [c][head-group]
    __shared__ float w[32];

    int tid = threadIdx.x;
    // phase 1: threads (c, hg) with hg in 0..3 covering 3 heads each
    if (tid < 128) {
        int c = tid & 31;
        int hg = tid >> 5;
        float acc = 0.f;
        if (c < len) {
            for (int h = hg * 3; h < hg * 3 + 3; h++) {
                const float* base = att + (((size_t)b * NHH + h) * LL + s) * LL + (s + c);
                for (int r = 0; r < len; r++) acc += base[(size_t)r * LL];
            }
        }
        part[c][hg] = acc;
    }
    __syncthreads();
    if (tid < 32) {
        // fixed-order sum over the 4 head groups -> deterministic
        w[tid] = ((part[tid][0] + part[tid][1]) + part[tid][2]) + part[tid][3];
    }
    __syncthreads();

    float scale = 1.f / (12.f * (float)len);
    const float* seqb = seq + ((size_t)b * LL + s) * HH;
    float* o = out + ((size_t)b * NROWS + 160 + k) * FF;
    for (int f = tid; f < HH; f += blockDim.x) {
        float acc = 0.f;
        for (int c = 0; c < len; c++) acc += w[c] * seqb[(size_t)c * HH + f];
        o[f] = acc * scale;
    }
}

// ---------------------------------------------------------------------------
// K5: node bank: entity logsumexp, mention gathers, type columns, zero pad
// ---------------------------------------------------------------------------
__global__ void k_nodes(const float* __restrict__ seq, const float* __restrict__ ttab,
                        const int* __restrict__ mpos, float* __restrict__ out) {
    int r = blockIdx.x;
    int b = blockIdx.y;
    float* o = out + ((size_t)b * NROWS + r) * FF;

    if (r < EE) {
        // entity: logsumexp over 4 member mention embeddings
        int p0 = mpos[(b * EE + r) * MPE + 0] + 1;
        int p1 = mpos[(b * EE + r) * MPE + 1] + 1;
        int p2 = mpos[(b * EE + r) * MPE + 2] + 1;
        int p3 = mpos[(b * EE + r) * MPE + 3] + 1;
        const float* s0 = seq + ((size_t)b * LL + p0) * HH;
        const float* s1 = seq + ((size_t)b * LL + p1) * HH;
        const float* s2 = seq + ((size_t)b * LL + p2) * HH;
        const float* s3 = seq + ((size_t)b * LL + p3) * HH;
        for (int f = threadIdx.x; f < HH; f += blockDim.x) {
            float x0 = s0[f], x1 = s1[f], x2 = s2[f], x3 = s3[f];
            float m = fmaxf(fmaxf(x0, x1), fmaxf(x2, x3));
            float sum = expf(x0 - m) + expf(x1 - m) + expf(x2 - m) + expf(x3 - m);
            o[f] = m + logf(sum);
        }
        for (int f = HH + threadIdx.x; f < FF; f += blockDim.x)
            o[f] = ttab[f - HH];                    // type 0
    } else if (r < EE + EMM) {
        int m = r - EE;
        int p = mpos[b * EMM + m] + 1;
        const float* s = seq + ((size_t)b * LL + p) * HH;
        for (int f = threadIdx.x; f < HH; f += blockDim.x) o[f] = s[f];
        for (int f = HH + threadIdx.x; f < FF; f += blockDim.x)
            o[f] = ttab[TYPED + f - HH];            // type 1
    } else if (r < 176) {
        for (int f = HH + threadIdx.x; f < FF; f += blockDim.x)
            o[f] = ttab[2 * TYPED + f - HH];        // type 2 (cols 0..767 by k_link)
    } else {
        for (int f = HH + threadIdx.x; f < FF; f += blockDim.x)
            o[f] = 0.f;                              // ctx zero pad (cols 0..767 by k_ctx)
    }
}

// ---------------------------------------------------------------------------
extern "C" void kernel_launch(void* const* d_in, const int* in_sizes, int n_in,
                              void* d_out, int out_size) {
    const float* seq   = (const float*)d_in[0];   // [4,1024,768]
    const float* att   = (const float*)d_in[1];   // [4,12,1024,1024]
    const float* ttab  = (const float*)d_in[2];   // [3,20]
    const int*   mpos  = (const int*)d_in[3];     // [4,32,4]
    const int*   lstart= (const int*)d_in[4];     // [4,16]
    const int*   llen  = (const int*)d_in[5];     // [4,16]
    float* out = (float*)d_out;

    k_mention_att<<<dim3(EMM, BB), 256>>>(att, mpos);
    k_entity_att<<<dim3(EE, BB), 256>>>();
    k_ctx<<<dim3(HH / TH, NA / TN, BB), 256>>>(seq, out);
    k_link<<<dim3(KLNK, BB), 256>>>(att, seq, lstart, llen, out);
    k_nodes<<<dim3(NROWS, BB), 256>>>(seq, ttab, mpos, out);
}

// round 2
// speedup vs baseline: 1.3515x; 1.3515x over previous
#include <cuda_runtime.h>
#include <math.h>

#define BB 4
#define LL 1024
#define HH 768
#define NHH 12
#define EE 32
#define MPE 4
#define EMM 128
#define KLNK 16
#define TYPED 20
#define NROWS 336
#define FF (HH + TYPED)      // 788
#define NA 160               // att rows per batch (E + EM)

// scratch
__device__ float g_att[BB * NA * LL];   // head-mean attention rows
__device__ float g_rs[BB * NA];         // row sums

// packed fp32x2 FMA (Blackwell): d = a*b + d, elementwise on 2 packed floats
__device__ __forceinline__ void fma2(unsigned long long& d,
                                     unsigned long long a, unsigned long long b) {
    asm("fma.rn.f32x2 %0, %1, %2, %0;" : "+l"(d) : "l"(a), "l"(b));
}

// ---------------------------------------------------------------------------
// K1: fused mention + entity attention rows (one block per entity).
// Each thread owns 4 consecutive l (float4). 256 threads * 4 = 1024 = L.
// ---------------------------------------------------------------------------
__global__ void k_ment_ent(const float* __restrict__ att,
                           const int* __restrict__ mpos) {
    int e = blockIdx.x;
    int b = blockIdx.y;
    int tid = threadIdx.x;
    int l4 = tid * 4;

    const float* attb = att + (size_t)b * NHH * LL * LL;
    float* rowbase = g_att + ((size_t)b * NA) * LL;

    float4 esum = make_float4(0.f, 0.f, 0.f, 0.f);
    float part[MPE];

#pragma unroll
    for (int mp = 0; mp < MPE; mp++) {
        int p = mpos[(b * EE + e) * MPE + mp] + 1;
        const float* rp = attb + (size_t)p * LL + l4;
        float4 acc = make_float4(0.f, 0.f, 0.f, 0.f);
#pragma unroll
        for (int h = 0; h < NHH; h++) {
            float4 v = *(const float4*)(rp + (size_t)h * LL * LL);
            acc.x += v.x; acc.y += v.y; acc.z += v.z; acc.w += v.w;
        }
        const float inv12 = 1.f / 12.f;
        acc.x *= inv12; acc.y *= inv12; acc.z *= inv12; acc.w *= inv12;
        *(float4*)(rowbase + ((size_t)(EE + e * MPE + mp)) * LL + l4) = acc;
        part[mp] = acc.x + acc.y + acc.z + acc.w;
        esum.x += acc.x; esum.y += acc.y; esum.z += acc.z; esum.w += acc.w;
    }
    esum.x *= 0.25f; esum.y *= 0.25f; esum.z *= 0.25f; esum.w *= 0.25f;
    *(float4*)(rowbase + (size_t)e * LL + l4) = esum;

    __shared__ float4 red[256];
    red[tid] = make_float4(part[0], part[1], part[2], part[3]);
    __syncthreads();
    for (int off = 128; off > 0; off >>= 1) {
        if (tid < off) {
            float4 a = red[tid], c = red[tid + off];
            red[tid] = make_float4(a.x + c.x, a.y + c.y, a.z + c.z, a.w + c.w);
        }
        __syncthreads();
    }
    if (tid == 0) {
        float4 r = red[0];
        g_rs[b * NA + EE + e * MPE + 0] = r.x;
        g_rs[b * NA + EE + e * MPE + 1] = r.y;
        g_rs[b * NA + EE + e * MPE + 2] = r.z;
        g_rs[b * NA + EE + e * MPE + 3] = r.w;
        g_rs[b * NA + e] = 0.25f * (r.x + r.y + r.z + r.w);
    }
}

// ---------------------------------------------------------------------------
// K2: context GEMM: ctx[n,h] = (1/(rs+1e-5)) * sum_l g_att[b,n,l]*seq[b,l,h]
// 128 threads, TN=32 x TH=128 tile, 4n x 8h microtile, packed f32x2 FMA.
// grid = (768/128, 640/32) = (6, 20)
// ---------------------------------------------------------------------------
#define TN 32
#define TH 128
#define TL 32
__global__ void __launch_bounds__(128, 1) k_ctx(const float* __restrict__ seq,
                                                float* __restrict__ out) {
    int ng = blockIdx.y * TN;            // global n row over 640
    int b = ng / NA;
    int n0 = ng % NA;
    int h0 = blockIdx.x * TH;

    __shared__ float2 As2[TN][TL + 1];   // duplicated {a,a}, padded vs bank conflicts
    __shared__ float Bs[TL][TH];
    __shared__ float inv[TN];

    int tid = threadIdx.x;
    if (tid < TN) inv[tid] = 1.f / (g_rs[b * NA + n0 + tid] + 1e-5f);

    int nl = (tid >> 4) * 4;             // 8 n-groups of 4 rows
    int hc = (tid & 15) * 8;             // 16 h-groups of 8 cols

    const float* attb = g_att + (size_t)(b * NA + n0) * LL;
    const float* seqb = seq + (size_t)b * LL * HH;

    unsigned long long acc[4][4];
#pragma unroll
    for (int i = 0; i < 4; i++)
#pragma unroll
        for (int j = 0; j < 4; j++) acc[i][j] = 0ull;

    for (int l0 = 0; l0 < LL; l0 += TL) {
        __syncthreads();
#pragma unroll
        for (int it = 0; it < 8; it++) {
            int idx = tid + it * 128;     // 0..1023
            int n = idx >> 5, l = idx & 31;
            float v = attb[(size_t)n * LL + l0 + l];
            As2[n][l] = make_float2(v, v);
        }
#pragma unroll
        for (int it = 0; it < 8; it++) {
            int slot = tid + it * 128;    // 1024 float4 slots
            int l = slot >> 5, hq = (slot & 31) * 4;
            *(float4*)&Bs[l][hq] = *(const float4*)&seqb[(size_t)(l0 + l) * HH + h0 + hq];
        }
        __syncthreads();
#pragma unroll 8
        for (int l = 0; l < TL; l++) {
            ulonglong2 B0 = *(const ulonglong2*)&Bs[l][hc];
            ulonglong2 B1 = *(const ulonglong2*)&Bs[l][hc + 4];
#pragma unroll
            for (int i = 0; i < 4; i++) {
                unsigned long long a =
                    *(const unsigned long long*)&As2[nl + i][l];
                fma2(acc[i][0], a, B0.x);
                fma2(acc[i][1], a, B0.y);
                fma2(acc[i][2], a, B1.x);
                fma2(acc[i][3], a, B1.y);
            }
        }
    }

#pragma unroll
    for (int i = 0; i < 4; i++) {
        float s = inv[nl + i];
        float o[8];
#pragma unroll
        for (int j = 0; j < 4; j++) {
            float2 f = *(float2*)&acc[i][j];
            o[2 * j]     = f.x * s;
            o[2 * j + 1] = f.y * s;
        }
        float* op = out + ((size_t)b * NROWS + 176 + n0 + nl + i) * FF + h0 + hc;
        *(float4*)op       = make_float4(o[0], o[1], o[2], o[3]);
        *(float4*)(op + 4) = make_float4(o[4], o[5], o[6], o[7]);
    }
}

// ---------------------------------------------------------------------------
// K3: link span pooling — parallel (h,r) across 8 groups x 32 c-lanes,
// fixed-order reductions (deterministic).
// ---------------------------------------------------------------------------
__global__ void k_link(const float* __restrict__ att, const float* __restrict__ seq,
                       const int* __restrict__ lstart, const int* __restrict__ llen,
                       float* __restrict__ out) {
    int k = blockIdx.x;
    int b = blockIdx.y;
    int s = lstart[b * KLNK + k] + 1;
    int len = llen[b * KLNK + k] + 1;   // 1..31

    __shared__ float part[8][32];
    __shared__ float w[32];

    int tid = threadIdx.x;
    int g = tid >> 5;                   // 0..7
    int c = tid & 31;

    float acc = 0.f;
    if (c < len) {
        for (int h = 0; h < NHH; h++) {
            const float* base = att + (((size_t)b * NHH + h) * LL + s) * LL + s + c;
            for (int r = g; r < len; r += 8) acc += base[(size_t)r * LL];
        }
    }
    part[g][c] = acc;
    __syncthreads();
    if (tid < 32) {
        float sum = 0.f;
#pragma unroll
        for (int gg = 0; gg < 8; gg++) sum += part[gg][tid];  // fixed order
        w[tid] = sum;
    }
    __syncthreads();

    float scale = 1.f / (12.f * (float)len);
    const float* seqb = seq + ((size_t)b * LL + s) * HH;
    float* o = out + ((size_t)b * NROWS + 160 + k) * FF;
    for (int f = tid; f < HH; f += blockDim.x) {
        float a = 0.f;
        for (int cc = 0; cc < len; cc++) a += w[cc] * seqb[(size_t)cc * HH + f];
        o[f] = a * scale;
    }
}

// ---------------------------------------------------------------------------
// K4: node bank: entity logsumexp, mention gathers, type columns, zero pad
// ---------------------------------------------------------------------------
__global__ void k_nodes(const float* __restrict__ seq, const float* __restrict__ ttab,
                        const int* __restrict__ mpos, float* __restrict__ out) {
    int r = blockIdx.x;
    int b = blockIdx.y;
    float* o = out + ((size_t)b * NROWS + r) * FF;

    if (r < EE) {
        int p0 = mpos[(b * EE + r) * MPE + 0] + 1;
        int p1 = mpos[(b * EE + r) * MPE + 1] + 1;
        int p2 = mpos[(b * EE + r) * MPE + 2] + 1;
        int p3 = mpos[(b * EE + r) * MPE + 3] + 1;
        const float* s0 = seq + ((size_t)b * LL + p0) * HH;
        const float* s1 = seq + ((size_t)b * LL + p1) * HH;
        const float* s2 = seq + ((size_t)b * LL + p2) * HH;
        const float* s3 = seq + ((size_t)b * LL + p3) * HH;
        for (int f = threadIdx.x; f < HH; f += blockDim.x) {
            float x0 = s0[f], x1 = s1[f], x2 = s2[f], x3 = s3[f];
            float m = fmaxf(fmaxf(x0, x1), fmaxf(x2, x3));
            float sum = expf(x0 - m) + expf(x1 - m) + expf(x2 - m) + expf(x3 - m);
            o[f] = m + logf(sum);
        }
        for (int f = HH + threadIdx.x; f < FF; f += blockDim.x)
            o[f] = ttab[f - HH];
    } else if (r < EE + EMM) {
        int m = r - EE;
        int p = mpos[b * EMM + m] + 1;
        const float* s = seq + ((size_t)b * LL + p) * HH;
        for (int f = threadIdx.x; f < HH; f += blockDim.x) o[f] = s[f];
        for (int f = HH + threadIdx.x; f < FF; f += blockDim.x)
            o[f] = ttab[TYPED + f - HH];
    } else if (r < 176) {
        for (int f = HH + threadIdx.x; f < FF; f += blockDim.x)
            o[f] = ttab[2 * TYPED + f - HH];
    } else {
        for (int f = HH + threadIdx.x; f < FF; f += blockDim.x)
            o[f] = 0.f;
    }
}

// ---------------------------------------------------------------------------
extern "C" void kernel_launch(void* const* d_in, const int* in_sizes, int n_in,
                              void* d_out, int out_size) {
    const float* seq    = (const float*)d_in[0];
    const float* att    = (const float*)d_in[1];
    const float* ttab   = (const float*)d_in[2];
    const int*   mpos   = (const int*)d_in[3];
    const int*   lstart = (const int*)d_in[4];
    const int*   llen   = (const int*)d_in[5];
    float* out = (float*)d_out;

    k_ment_ent<<<dim3(EE, BB), 256>>>(att, mpos);
    k_ctx<<<dim3(HH / TH, (BB * NA) / TN), 128>>>(seq, out);
    k_link<<<dim3(KLNK, BB), 256>>>(att, seq, lstart, llen, out);
    k_nodes<<<dim3(NROWS, BB), 256>>>(seq, ttab, mpos, out);
}

// round 3
// speedup vs baseline: 1.5882x; 1.1751x over previous
#include <cuda_runtime.h>
#include <math.h>

#define BB 4
#define LL 1024
#define HH 768
#define NHH 12
#define EE 32
#define MPE 4
#define EMM 128
#define KLNK 16
#define TYPED 20
#define NROWS 336
#define FF (HH + TYPED)      // 788
#define NA 160               // E + EM

typedef unsigned long long ull;

// scratch: mention head-mean attention rows + their row sums
__device__ float g_att[BB * EMM * LL];   // [b][m][l]
__device__ float g_rs[BB * EMM];

__device__ __forceinline__ void fma2(ull& d, ull a, ull b) {
    asm("fma.rn.f32x2 %0, %1, %2, %0;" : "+l"(d) : "l"(a), "l"(b));
}

// ---------------------------------------------------------------------------
// K1 "front": fused link-span pooling + mention attention rows + node bank.
// Block roles: [0,64) link, [64,576) mention, [576,1216) nodes.
// ---------------------------------------------------------------------------
__global__ void __launch_bounds__(256) k_front(
    const float* __restrict__ att, const float* __restrict__ seq,
    const float* __restrict__ ttab, const int* __restrict__ mpos,
    const int* __restrict__ lstart, const int* __restrict__ llen,
    float* __restrict__ out)
{
    __shared__ float sh[8 * 32 + 32];
    int bid = blockIdx.x;
    int tid = threadIdx.x;

    if (bid < 64) {
        // ---------------- link span pooling ----------------
        int k = bid & 15, b = bid >> 4;
        int s = lstart[b * KLNK + k] + 1;
        int len = llen[b * KLNK + k] + 1;          // 1..31

        float* part = sh;                           // [8][32]
        float* w = sh + 256;                        // [32]
        int g = tid >> 5, c = tid & 31;

        float acc = 0.f;
        if (c < len) {
            for (int h = 0; h < NHH; h++) {
                const float* base = att + (((size_t)b * NHH + h) * LL + s) * LL + s + c;
                for (int r = g; r < len; r += 8) acc += base[(size_t)r * LL];
            }
        }
        part[g * 32 + c] = acc;
        __syncthreads();
        if (tid < 32) {
            float sum = 0.f;
#pragma unroll
            for (int gg = 0; gg < 8; gg++) sum += part[gg * 32 + tid];   // fixed order
            w[tid] = sum;
        }
        __syncthreads();

        float scale = 1.f / (12.f * (float)len);
        const float* seqb = seq + ((size_t)b * LL + s) * HH;
        float* o = out + ((size_t)b * NROWS + 160 + k) * FF;
        for (int f = tid; f < HH; f += 256) {
            float a = 0.f;
            for (int cc = 0; cc < len; cc++) a += w[cc] * seqb[(size_t)cc * HH + f];
            o[f] = a * scale;
        }
        if (tid < TYPED) o[HH + tid] = ttab[2 * TYPED + tid];   // type 2
    } else if (bid < 576) {
        // ---------------- mention attention row (head mean) + rowsum --------
        int i = bid - 64;
        int m = i & 127, b = i >> 7;
        int p = mpos[b * EMM + m] + 1;
        const float* rp = att + (size_t)b * NHH * LL * LL + (size_t)p * LL + tid * 4;

        float4 acc = make_float4(0.f, 0.f, 0.f, 0.f);
#pragma unroll
        for (int h = 0; h < NHH; h++) {
            float4 v = *(const float4*)(rp + (size_t)h * LL * LL);
            acc.x += v.x; acc.y += v.y; acc.z += v.z; acc.w += v.w;
        }
        const float inv12 = 1.f / 12.f;
        acc.x *= inv12; acc.y *= inv12; acc.z *= inv12; acc.w *= inv12;
        *(float4*)&g_att[((size_t)b * EMM + m) * LL + tid * 4] = acc;

        float s = (acc.x + acc.y) + (acc.z + acc.w);
#pragma unroll
        for (int off = 16; off > 0; off >>= 1)
            s += __shfl_down_sync(0xffffffffu, s, off);
        if ((tid & 31) == 0) sh[tid >> 5] = s;
        __syncthreads();
        if (tid == 0) {
            float t = 0.f;
#pragma unroll
            for (int ww = 0; ww < 8; ww++) t += sh[ww];       // fixed order
            g_rs[b * EMM + m] = t;
        }
    } else {
        // ---------------- node bank rows 0..159 ----------------
        int i = bid - 576;
        int r = i % 160, b = i / 160;
        float* o = out + ((size_t)b * NROWS + r) * FF;

        if (r < EE) {
            const int* mp = mpos + (b * EE + r) * MPE;
            int p0 = mp[0] + 1, p1 = mp[1] + 1, p2 = mp[2] + 1, p3 = mp[3] + 1;
            if (tid < 192) {
                int f = tid * 4;
                float4 x0 = *(const float4*)(seq + ((size_t)b * LL + p0) * HH + f);
                float4 x1 = *(const float4*)(seq + ((size_t)b * LL + p1) * HH + f);
                float4 x2 = *(const float4*)(seq + ((size_t)b * LL + p2) * HH + f);
                float4 x3 = *(const float4*)(seq + ((size_t)b * LL + p3) * HH + f);
                float4 res;
                {
                    float m0 = fmaxf(fmaxf(x0.x, x1.x), fmaxf(x2.x, x3.x));
                    res.x = m0 + logf(expf(x0.x-m0)+expf(x1.x-m0)+expf(x2.x-m0)+expf(x3.x-m0));
                    float m1 = fmaxf(fmaxf(x0.y, x1.y), fmaxf(x2.y, x3.y));
                    res.y = m1 + logf(expf(x0.y-m1)+expf(x1.y-m1)+expf(x2.y-m1)+expf(x3.y-m1));
                    float m2 = fmaxf(fmaxf(x0.z, x1.z), fmaxf(x2.z, x3.z));
                    res.z = m2 + logf(expf(x0.z-m2)+expf(x1.z-m2)+expf(x2.z-m2)+expf(x3.z-m2));
                    float m3 = fmaxf(fmaxf(x0.w, x1.w), fmaxf(x2.w, x3.w));
                    res.w = m3 + logf(expf(x0.w-m3)+expf(x1.w-m3)+expf(x2.w-m3)+expf(x3.w-m3));
                }
                *(float4*)(o + f) = res;
            } else if (tid < 192 + TYPED) {
                o[HH + tid - 192] = ttab[tid - 192];              // type 0
            }
        } else {
            int m = r - EE;
            int p = mpos[b * EMM + m] + 1;
            if (tid < 192) {
                *(float4*)(o + tid * 4) =
                    *(const float4*)(seq + ((size_t)b * LL + p) * HH + tid * 4);
            } else if (tid < 192 + TYPED) {
                o[HH + tid - 192] = ttab[TYPED + tid - 192];      // type 1
            }
        }
    }
}

// ---------------------------------------------------------------------------
// K2: context GEMM. ctx[n,h] = inv[n] * sum_l A[b,n,l]*seq[b,l,h]
// A rows: n<32 -> entity = mean of 4 mention rows (synthesized in loader);
//         else mention row (n-32). inv from g_rs.
// Tile TN=32 x TH=128, TL=32, 256 thr, double-buffered, f32x2 FMA.
// Microtile: warp -> 4 n-rows, lane -> 4 h. grid (6, 20).
// ---------------------------------------------------------------------------
#define TN 32
#define TH 128
#define TL 32
__global__ void __launch_bounds__(256, 1) k_ctx(const float* __restrict__ seq,
                                                float* __restrict__ out) {
    int ng = blockIdx.y * TN;
    int b = ng / NA;
    int n0 = ng % NA;
    int h0 = blockIdx.x * TH;
    bool entBlock = (n0 == 0);

    __shared__ float2 As2[2][TN][TL + 1];
    __shared__ float Bs[2][TL][TH + 4];
    __shared__ float s_inv[TN];

    int tid = threadIdx.x;
    if (tid < TN) {
        float rs;
        if (entBlock) {
            const float* r = g_rs + b * EMM + tid * MPE;
            rs = 0.25f * (((r[0] + r[1]) + r[2]) + r[3]);
        } else {
            rs = g_rs[b * EMM + (n0 - EE) + tid];
        }
        s_inv[tid] = 1.f / (rs + 1e-5f);
    }

    const float* attb = g_att + (size_t)b * EMM * LL;
    const float* seqb = seq + (size_t)b * LL * HH;

    int w = tid >> 5, lane = tid & 31;
    int nw = w * 4;
    int hq = lane * 4;

    ull acc[4][2];
#pragma unroll
    for (int i = 0; i < 4; i++) { acc[i][0] = 0ull; acc[i][1] = 0ull; }

    auto loadA = [&](int buf, int l0) {
#pragma unroll
        for (int it = 0; it < 4; it++) {
            int idx = tid + it * 256;
            int n = idx >> 5, l = idx & 31;
            float v;
            if (entBlock) {
                const float* p = attb + (size_t)(n * MPE) * LL + l0 + l;
                v = 0.25f * (((p[0] + p[LL]) + p[2 * LL]) + p[3 * LL]);
            } else {
                v = attb[(size_t)(n0 - EE + n) * LL + l0 + l];
            }
            As2[buf][n][l] = make_float2(v, v);
        }
    };
    auto loadB = [&](int buf, int l0) {
#pragma unroll
        for (int it = 0; it < 4; it++) {
            int slot = tid + it * 256;
            int l = slot >> 5, h4 = (slot & 31) * 4;
            *(float4*)&Bs[buf][l][h4] =
                *(const float4*)&seqb[(size_t)(l0 + l) * HH + h0 + h4];
        }
    };

    loadA(0, 0);
    loadB(0, 0);
    __syncthreads();

    for (int c = 0; c < LL / TL; c++) {
        int cur = c & 1;
        if (c + 1 < LL / TL) {
            loadA(cur ^ 1, (c + 1) * TL);
            loadB(cur ^ 1, (c + 1) * TL);
        }
#pragma unroll 8
        for (int l = 0; l < TL; l++) {
            ulonglong2 bv = *(const ulonglong2*)&Bs[cur][l][hq];
#pragma unroll
            for (int i = 0; i < 4; i++) {
                ull a = *(const ull*)&As2[cur][nw + i][l];
                fma2(acc[i][0], a, bv.x);
                fma2(acc[i][1], a, bv.y);
            }
        }
        __syncthreads();
    }

#pragma unroll
    for (int i = 0; i < 4; i++) {
        float s = s_inv[nw + i];
        float2 f0 = *(float2*)&acc[i][0];
        float2 f1 = *(float2*)&acc[i][1];
        float4 v = make_float4(f0.x * s, f0.y * s, f1.x * s, f1.y * s);
        *(float4*)(out + ((size_t)b * NROWS + 176 + n0 + nw + i) * FF + h0 + hq) = v;
    }

    // last h-block also zero-pads the TYPE_DIM tail of the ctx rows
    if (blockIdx.x == (HH / TH) - 1 && tid < TN) {
        float* o = out + ((size_t)b * NROWS + 176 + n0 + tid) * FF + HH;
#pragma unroll
        for (int j = 0; j < TYPED; j++) o[j] = 0.f;
    }
}

// ---------------------------------------------------------------------------
extern "C" void kernel_launch(void* const* d_in, const int* in_sizes, int n_in,
                              void* d_out, int out_size) {
    const float* seq    = (const float*)d_in[0];
    const float* att    = (const float*)d_in[1];
    const float* ttab   = (const float*)d_in[2];
    const int*   mpos   = (const int*)d_in[3];
    const int*   lstart = (const int*)d_in[4];
    const int*   llen   = (const int*)d_in[5];
    float* out = (float*)d_out;

    k_front<<<64 + 512 + 640, 256>>>(att, seq, ttab, mpos, lstart, llen, out);
    k_ctx<<<dim3(HH / TH, (BB * NA) / TN), 256>>>(seq, out);
}

// round 4
// speedup vs baseline: 2.8293x; 1.7815x over previous
#include <cuda_runtime.h>
#include <math.h>

#define BB 4
#define LL 1024
#define HH 768
#define NHH 12
#define EE 32
#define MPE 4
#define EMM 128
#define KLNK 16
#define TYPED 20
#define NROWS 336
#define FF (HH + TYPED)      // 788
#define NA 160

typedef unsigned long long ull;

// scratch
__device__ float g_att[BB * EMM * LL];          // mention head-mean att rows
__device__ float g_rs[BB * EMM];                // mention row sums
__device__ float g_part[3][BB][EMM][HH];        // split-K raw GEMM partials

__device__ __forceinline__ void fma2(ull& d, ull a, ull b) {
    asm("fma.rn.f32x2 %0, %1, %2, %0;" : "+l"(d) : "l"(a), "l"(b));
}
__device__ __forceinline__ ull dup2(float a) {
    ull d;
    asm("mov.b64 %0, {%1, %1};" : "=l"(d) : "f"(a));
    return d;
}

// ---------------------------------------------------------------------------
// K1 "front": link-span pooling + mention attention rows + node bank.
// Block roles: [0,64) link, [64,576) mention, [576,1216) nodes.
// ---------------------------------------------------------------------------
__global__ void __launch_bounds__(256) k_front(
    const float* __restrict__ att, const float* __restrict__ seq,
    const float* __restrict__ ttab, const int* __restrict__ mpos,
    const int* __restrict__ lstart, const int* __restrict__ llen,
    float* __restrict__ out)
{
    __shared__ float sh[8 * 32 + 32];
    int bid = blockIdx.x;
    int tid = threadIdx.x;

    if (bid < 64) {
        // ---------------- link span pooling ----------------
        int k = bid & 15, b = bid >> 4;
        int s = lstart[b * KLNK + k] + 1;
        int len = llen[b * KLNK + k] + 1;          // 1..31

        float* part = sh;
        float* w = sh + 256;
        int g = tid >> 5, c = tid & 31;

        float acc = 0.f;
        if (c < len) {
            for (int h = 0; h < NHH; h++) {
                const float* base = att + (((size_t)b * NHH + h) * LL + s) * LL + s + c;
                for (int r = g; r < len; r += 8) acc += base[(size_t)r * LL];
            }
        }
        part[g * 32 + c] = acc;
        __syncthreads();
        if (tid < 32) {
            float sum = 0.f;
#pragma unroll
            for (int gg = 0; gg < 8; gg++) sum += part[gg * 32 + tid];   // fixed order
            w[tid] = sum;
        }
        __syncthreads();

        float scale = 1.f / (12.f * (float)len);
        const float* seqb = seq + ((size_t)b * LL + s) * HH;
        float* o = out + ((size_t)b * NROWS + 160 + k) * FF;
        for (int f = tid; f < HH; f += 256) {
            float a = 0.f;
            for (int cc = 0; cc < len; cc++) a += w[cc] * seqb[(size_t)cc * HH + f];
            o[f] = a * scale;
        }
        if (tid < TYPED) o[HH + tid] = ttab[2 * TYPED + tid];   // type 2
    } else if (bid < 576) {
        // ---------------- mention attention row (head mean) + rowsum --------
        int i = bid - 64;
        int m = i & 127, b = i >> 7;
        int p = mpos[b * EMM + m] + 1;
        const float* rp = att + (size_t)b * NHH * LL * LL + (size_t)p * LL + tid * 4;

        float4 acc = make_float4(0.f, 0.f, 0.f, 0.f);
#pragma unroll
        for (int h = 0; h < NHH; h++) {
            float4 v = *(const float4*)(rp + (size_t)h * LL * LL);
            acc.x += v.x; acc.y += v.y; acc.z += v.z; acc.w += v.w;
        }
        const float inv12 = 1.f / 12.f;
        acc.x *= inv12; acc.y *= inv12; acc.z *= inv12; acc.w *= inv12;
        *(float4*)&g_att[((size_t)b * EMM + m) * LL + tid * 4] = acc;

        float s = (acc.x + acc.y) + (acc.z + acc.w);
#pragma unroll
        for (int off = 16; off > 0; off >>= 1)
            s += __shfl_down_sync(0xffffffffu, s, off);
        if ((tid & 31) == 0) sh[tid >> 5] = s;
        __syncthreads();
        if (tid == 0) {
            float t = 0.f;
#pragma unroll
            for (int ww = 0; ww < 8; ww++) t += sh[ww];          // fixed order
            g_rs[b * EMM + m] = t;
        }
    } else {
        // ---------------- node bank rows 0..159 ----------------
        int i = bid - 576;
        int r = i % 160, b = i / 160;
        float* o = out + ((size_t)b * NROWS + r) * FF;

        if (r < EE) {
            const int* mp = mpos + (b * EE + r) * MPE;
            int p0 = mp[0] + 1, p1 = mp[1] + 1, p2 = mp[2] + 1, p3 = mp[3] + 1;
            if (tid < 192) {
                int f = tid * 4;
                float4 x0 = *(const float4*)(seq + ((size_t)b * LL + p0) * HH + f);
                float4 x1 = *(const float4*)(seq + ((size_t)b * LL + p1) * HH + f);
                float4 x2 = *(const float4*)(seq + ((size_t)b * LL + p2) * HH + f);
                float4 x3 = *(const float4*)(seq + ((size_t)b * LL + p3) * HH + f);
                float4 res;
                float m0 = fmaxf(fmaxf(x0.x, x1.x), fmaxf(x2.x, x3.x));
                res.x = m0 + logf(expf(x0.x-m0)+expf(x1.x-m0)+expf(x2.x-m0)+expf(x3.x-m0));
                float m1 = fmaxf(fmaxf(x0.y, x1.y), fmaxf(x2.y, x3.y));
                res.y = m1 + logf(expf(x0.y-m1)+expf(x1.y-m1)+expf(x2.y-m1)+expf(x3.y-m1));
                float m2 = fmaxf(fmaxf(x0.z, x1.z), fmaxf(x2.z, x3.z));
                res.z = m2 + logf(expf(x0.z-m2)+expf(x1.z-m2)+expf(x2.z-m2)+expf(x3.z-m2));
                float m3 = fmaxf(fmaxf(x0.w, x1.w), fmaxf(x2.w, x3.w));
                res.w = m3 + logf(expf(x0.w-m3)+expf(x1.w-m3)+expf(x2.w-m3)+expf(x3.w-m3));
                *(float4*)(o + f) = res;
            } else if (tid < 192 + TYPED) {
                o[HH + tid - 192] = ttab[tid - 192];              // type 0
            }
        } else {
            int m = r - EE;
            int p = mpos[b * EMM + m] + 1;
            if (tid < 192) {
                *(float4*)(o + tid * 4) =
                    *(const float4*)(seq + ((size_t)b * LL + p) * HH + tid * 4);
            } else if (tid < 192 + TYPED) {
                o[HH + tid - 192] = ttab[TYPED + tid - 192];      // type 1
            }
        }
    }
}

// ---------------------------------------------------------------------------
// K2: split-K raw context GEMM over MENTION rows only.
//   g_part[s][b][m][h] = sum_{l in chunk s} g_att[b][m][l] * seq[b][l][h]
// Tile: 64n x 128h, TL=32, 256 thr. Warp = 8 n-rows, lane = 4 h.
// A read as float4 over l (broadcast), packed to {a,a} via mov.b64.
// Grid (6, 8, 3): h-blocks x (b,n0) x l-chunks {352,352,320}.
// ---------------------------------------------------------------------------
#define CTN 64
#define CTH 128
#define CTL 32
__global__ void __launch_bounds__(256, 1) k_ctx(const float* __restrict__ seq) {
    int h0 = blockIdx.x * CTH;
    int nb = blockIdx.y;
    int b = nb >> 1;
    int n0 = (nb & 1) * CTN;         // mention row base within batch
    int s = blockIdx.z;
    int l_start = s * 352;
    int iters = (s == 2) ? 10 : 11;  // *32 = 320 / 352

    __shared__ float As[2][CTN][CTL];
    __shared__ float Bs[2][CTL][CTH];

    int tid = threadIdx.x;
    int w = tid >> 5, lane = tid & 31;
    int nw = w * 8;
    int hq = lane * 4;

    const float* attb = g_att + ((size_t)b * EMM + n0) * LL;
    const float* seqb = seq + (size_t)b * LL * HH;

    ull acc[8][2];
#pragma unroll
    for (int i = 0; i < 8; i++) { acc[i][0] = 0ull; acc[i][1] = 0ull; }

    auto loadA = [&](int buf, int l0) {
#pragma unroll
        for (int it = 0; it < 2; it++) {
            int idx = tid + it * 256;          // 512 float4 slots
            int n = idx >> 3, l4 = (idx & 7) * 4;
            *(float4*)&As[buf][n][l4] = *(const float4*)&attb[(size_t)n * LL + l0 + l4];
        }
    };
    auto loadB = [&](int buf, int l0) {
#pragma unroll
        for (int it = 0; it < 4; it++) {
            int slot = tid + it * 256;         // 1024 float4 slots
            int l = slot >> 5, h4 = (slot & 31) * 4;
            *(float4*)&Bs[buf][l][h4] = *(const float4*)&seqb[(size_t)(l0 + l) * HH + h0 + h4];
        }
    };

    loadA(0, l_start);
    loadB(0, l_start);
    __syncthreads();

    for (int c = 0; c < iters; c++) {
        int cur = c & 1;
        if (c + 1 < iters) {
            loadA(cur ^ 1, l_start + (c + 1) * CTL);
            loadB(cur ^ 1, l_start + (c + 1) * CTL);
        }
#pragma unroll
        for (int l4 = 0; l4 < CTL / 4; l4++) {
            float4 a4[8];
#pragma unroll
            for (int i = 0; i < 8; i++)
                a4[i] = *(const float4*)&As[cur][nw + i][l4 * 4];   // broadcast LDS.128
#pragma unroll
            for (int j = 0; j < 4; j++) {
                ulonglong2 bv = *(const ulonglong2*)&Bs[cur][l4 * 4 + j][hq];
#pragma unroll
                for (int i = 0; i < 8; i++) {
                    float a = (j == 0) ? a4[i].x : (j == 1) ? a4[i].y
                             : (j == 2) ? a4[i].z : a4[i].w;
                    ull ad = dup2(a);
                    fma2(acc[i][0], ad, bv.x);
                    fma2(acc[i][1], ad, bv.y);
                }
            }
        }
        __syncthreads();
    }

#pragma unroll
    for (int i = 0; i < 8; i++) {
        float2 f0 = *(float2*)&acc[i][0];
        float2 f1 = *(float2*)&acc[i][1];
        *(float4*)&g_part[s][b][n0 + nw + i][h0 + hq] =
            make_float4(f0.x, f0.y, f1.x, f1.y);
    }
}

// ---------------------------------------------------------------------------
// K3 epilogue: reduce split-K partials (fixed order), normalize, write ctx
// rows 176..335 + zero type pad. Entity rows synthesized from raw mention
// sums: e_ctx = (sum_mp raw)/ (sum_mp rs + 4e-5).
// ---------------------------------------------------------------------------
__global__ void __launch_bounds__(224) k_epi(float* __restrict__ out) {
    int r = blockIdx.x % NA;
    int b = blockIdx.x / NA;
    int tid = threadIdx.x;
    float* o = out + ((size_t)b * NROWS + 176 + r) * FF;

    if (tid < 192) {
        int f = tid * 4;
        float4 v = make_float4(0.f, 0.f, 0.f, 0.f);
        float scale;
        if (r < EE) {
#pragma unroll
            for (int s = 0; s < 3; s++)
#pragma unroll
                for (int mp = 0; mp < MPE; mp++) {
                    float4 p = *(const float4*)&g_part[s][b][r * MPE + mp][f];
                    v.x += p.x; v.y += p.y; v.z += p.z; v.w += p.w;
                }
            const float* rs = g_rs + b * EMM + r * MPE;
            scale = 1.f / ((((rs[0] + rs[1]) + rs[2]) + rs[3]) + 4e-5f);
        } else {
            int m = r - EE;
#pragma unroll
            for (int s = 0; s < 3; s++) {
                float4 p = *(const float4*)&g_part[s][b][m][f];
                v.x += p.x; v.y += p.y; v.z += p.z; v.w += p.w;
            }
            scale = 1.f / (g_rs[b * EMM + m] + 1e-5f);
        }
        *(float4*)(o + f) = make_float4(v.x * scale, v.y * scale, v.z * scale, v.w * scale);
    } else if (tid < 192 + TYPED) {
        o[HH + tid - 192] = 0.f;
    }
}

// ---------------------------------------------------------------------------
extern "C" void kernel_launch(void* const* d_in, const int* in_sizes, int n_in,
                              void* d_out, int out_size) {
    const float* seq    = (const float*)d_in[0];
    const float* att    = (const float*)d_in[1];
    const float* ttab   = (const float*)d_in[2];
    const int*   mpos   = (const int*)d_in[3];
    const int*   lstart = (const int*)d_in[4];
    const int*   llen   = (const int*)d_in[5];
    float* out = (float*)d_out;

    k_front<<<64 + 512 + 640, 256>>>(att, seq, ttab, mpos, lstart, llen, out);
    k_ctx<<<dim3(HH / CTH, 2 * BB, 3), 256>>>(seq);
    k_epi<<<NA * BB, 224>>>(out);
}